// round 2
// baseline (speedup 1.0000x reference)
#include <cuda_runtime.h>

// DenseWarpLayer: bilinear warp, N=8, H=512, W=512, C=32 fp32.
// out[n,h,w,c] = bilerp(image, h - flow[...,0], w - flow[...,1]),
// floor clamped to [0,size-2], alphas clamped to [0,1].
//
// R2: 4 threads per pixel, each handling TWO float4 channel-quads
// (c4 and c4+4). Doubles per-thread memory-level parallelism
// (8 front-batched LDG.128) and halves redundant flow loads / index ALU.
// Streaming stores keep the write-once output from polluting L2
// (image row reuse lives there).

#define N_ 8
#define H_ 512
#define W_ 512
#define C4_ 8            // 32 channels = 8 float4
#define ROW4 (W_ * C4_)  // float4 units per image row = 4096

__device__ __forceinline__ float4 lerp2(const float4 tl, const float4 tr,
                                        const float4 bl, const float4 br,
                                        const float ax, const float ay)
{
    float4 r;
    float top, bot;
    top = tl.x + ax * (tr.x - tl.x); bot = bl.x + ax * (br.x - bl.x);
    r.x = top + ay * (bot - top);
    top = tl.y + ax * (tr.y - tl.y); bot = bl.y + ax * (br.y - bl.y);
    r.y = top + ay * (bot - top);
    top = tl.z + ax * (tr.z - tl.z); bot = bl.z + ax * (br.z - bl.z);
    r.z = top + ay * (bot - top);
    top = tl.w + ax * (tr.w - tl.w); bot = bl.w + ax * (br.w - bl.w);
    r.w = top + ay * (bot - top);
    return r;
}

__global__ __launch_bounds__(256)
void dense_warp_kernel(const float* __restrict__ image,
                       const float* __restrict__ flow,
                       float* __restrict__ out)
{
    // total threads = N*H*W*4 = 8,388,608 — exact grid, no bounds check
    const unsigned tid = blockIdx.x * 256u + threadIdx.x;

    const unsigned c4  = tid & 3u;          // quad pair: handles c4 and c4+4
    const unsigned pix = tid >> 2;          // linear (n,h,w)
    const unsigned w   = pix & (W_ - 1);
    const unsigned h   = (pix >> 9) & (H_ - 1);
    const unsigned n   = pix >> 18;

    const float2 fl = __ldg(reinterpret_cast<const float2*>(flow) + pix);

    const float qy = (float)h - fl.x;
    const float qx = (float)w - fl.y;

    float fyf = floorf(qy);
    float fxf = floorf(qx);
    fyf = fminf(fmaxf(fyf, 0.0f), (float)(H_ - 2));
    fxf = fminf(fmaxf(fxf, 0.0f), (float)(W_ - 2));

    const float ay = fminf(fmaxf(qy - fyf, 0.0f), 1.0f);
    const float ax = fminf(fmaxf(qx - fxf, 0.0f), 1.0f);

    const int iy = (int)fyf;
    const int ix = (int)fxf;

    const long long rb = (((long long)n * H_ + iy) * W_ + ix) * C4_ + c4;
    const float4* img4 = reinterpret_cast<const float4*>(image);

    // 8 independent 128-bit gathers, front-batched for MLP
    const float4 tl0 = __ldg(img4 + rb);
    const float4 tl1 = __ldg(img4 + rb + 4);
    const float4 tr0 = __ldg(img4 + rb + C4_);
    const float4 tr1 = __ldg(img4 + rb + C4_ + 4);
    const float4 bl0 = __ldg(img4 + rb + ROW4);
    const float4 bl1 = __ldg(img4 + rb + ROW4 + 4);
    const float4 br0 = __ldg(img4 + rb + ROW4 + C4_);
    const float4 br1 = __ldg(img4 + rb + ROW4 + C4_ + 4);

    const float4 r0 = lerp2(tl0, tr0, bl0, br0, ax, ay);
    const float4 r1 = lerp2(tl1, tr1, bl1, br1, ax, ay);

    float4* out4 = reinterpret_cast<float4*>(out);
    const long long ob = (long long)pix * C4_ + c4;
    __stcs(out4 + ob, r0);       // streaming: output is write-once
    __stcs(out4 + ob + 4, r1);
}

extern "C" void kernel_launch(void* const* d_in, const int* in_sizes, int n_in,
                              void* d_out, int out_size)
{
    const float* image = (const float*)d_in[0];
    const float* flow  = (const float*)d_in[1];
    float* out = (float*)d_out;

    // 8,388,608 threads / 256 = 32,768 blocks
    dense_warp_kernel<<<32768, 256>>>(image, flow, out);
}